// round 1
// baseline (speedup 1.0000x reference)
#include <cuda_runtime.h>

#define BDIM 16
#define NDIM 128
#define HDIM 256

#define A_STRIDE 260   // 128 rows of [j][h], padded, float4-aligned
#define B_STRIDE 68    // 256 rows of [h][k-chunk 64], padded

// scratch for xw = inputs @ W_atom  (2 MB, L2-resident)
__device__ float g_xw[BDIM * NDIM * HDIM];

// ---------------------------------------------------------------------------
// Kernel 1: xw[b,n,k] = sum_h inputs[b,n,h] * W_atom[h,k]
// 4 rows per block to amortize W_atom loads (L2-hot after first wave).
// ---------------------------------------------------------------------------
__global__ void __launch_bounds__(256, 4) xw_kernel(
    const float* __restrict__ inputs, const float* __restrict__ W_atom)
{
    __shared__ float s_in[4][HDIM];
    int row0 = blockIdx.x * 4;
    int t = threadIdx.x;
#pragma unroll
    for (int r = 0; r < 4; r++) s_in[r][t] = inputs[(row0 + r) * HDIM + t];
    __syncthreads();

    float a0 = 0.f, a1 = 0.f, a2 = 0.f, a3 = 0.f;
#pragma unroll 8
    for (int h = 0; h < HDIM; h++) {
        float w = W_atom[h * HDIM + t];
        a0 = fmaf(s_in[0][h], w, a0);
        a1 = fmaf(s_in[1][h], w, a1);
        a2 = fmaf(s_in[2][h], w, a2);
        a3 = fmaf(s_in[3][h], w, a3);
    }
    g_xw[(row0 + 0) * HDIM + t] = a0;
    g_xw[(row0 + 1) * HDIM + t] = a1;
    g_xw[(row0 + 2) * HDIM + t] = a2;
    g_xw[(row0 + 3) * HDIM + t] = a3;
}

// ---------------------------------------------------------------------------
// Kernel 2: one CTA per (b,i).
//   binproj = bin[b,i] @ W_bin   (128x256 @ 256x256, fp32 register tiling)
//   score[j] = sum_k relu(xw_i[k] + xw_j[k] + b_bin[k] + binproj[j,k]) * w_score[k]
//   out_ctx[b,i,:] = inputs[b,i,:] * (sum_j score[j] + N*b_score)
//   out_pair[b,i,j,:] = inputs[b,i,:] + inputs[b,j,:]
// ---------------------------------------------------------------------------
extern __shared__ float smem[];

__global__ void __launch_bounds__(256, 1) main_kernel(
    const float* __restrict__ inputs,
    const float* __restrict__ bin_features,
    const float* __restrict__ W_bin,
    const float* __restrict__ b_bin,
    const float* __restrict__ w_score,
    const float* __restrict__ b_score,
    float* __restrict__ out_ctx,
    float* __restrict__ out_pair)
{
    float* As      = smem;                       // 128 * 260
    float* Bs      = As + NDIM * A_STRIDE;       // 256 * 68
    float* base_s  = Bs + HDIM * B_STRIDE;       // 256  (xw_i + b_bin)
    float* wsc_s   = base_s + HDIM;              // 256
    float* ini_s   = wsc_s + HDIM;               // 256  (inputs[b,i,:])
    float* score_s = ini_s + HDIM;               // 128
    float* red_s   = score_s + NDIM;             // 8

    const int bi = blockIdx.x;                   // b*128 + i
    const int b  = bi >> 7;
    const int t  = threadIdx.x;
    const int tx = t & 15;                       // k-group (4 cols each)
    const int ty = t >> 4;                       // j-group (8 rows each)

    // small smem fills
    base_s[t]  = g_xw[bi * HDIM + t] + b_bin[t];
    wsc_s[t]   = w_score[t];
    ini_s[t]   = inputs[bi * HDIM + t];
    if (t < NDIM) score_s[t] = 0.f;

    // A tile: bin_features[b,i,:,:] -> smem, row-major [j][h], stride A_STRIDE
    const float4* gA = (const float4*)(bin_features + (size_t)bi * NDIM * HDIM);
#pragma unroll
    for (int idx = t; idx < NDIM * (HDIM / 4); idx += 256) {
        int j = idx >> 6, q = idx & 63;
        float4 v = gA[j * 64 + q];
        *(float4*)&As[j * A_STRIDE + q * 4] = v;
    }
    __syncthreads();  // ini_s and As ready

    // atom_pair writes — launch the DRAM stores early so they overlap compute
    {
        const float4* gin  = (const float4*)(inputs + (size_t)b * NDIM * HDIM);
        float4*       gp   = (float4*)(out_pair + (size_t)bi * NDIM * HDIM);
        const float4* ini4 = (const float4*)ini_s;
        for (int idx = t; idx < NDIM * (HDIM / 4); idx += 256) {
            int j = idx >> 6, q = idx & 63;
            float4 a = ini4[q];
            float4 c = gin[j * 64 + q];
            a.x += c.x; a.y += c.y; a.z += c.z; a.w += c.w;
            gp[idx] = a;
        }
    }

    const float* xwb = g_xw + (size_t)b * NDIM * HDIM;

    for (int kc = 0; kc < HDIM; kc += 64) {
        __syncthreads();  // previous chunk done reading Bs
        // Bs = W_bin[:, kc:kc+64]
        for (int idx = t; idx < HDIM * 16; idx += 256) {
            int h = idx >> 4, q = idx & 15;
            float4 v = *(const float4*)&W_bin[h * HDIM + kc + q * 4];
            *(float4*)&Bs[h * B_STRIDE + q * 4] = v;
        }
        __syncthreads();

        float acc[8][4];
#pragma unroll
        for (int jj = 0; jj < 8; jj++)
#pragma unroll
            for (int kk = 0; kk < 4; kk++) acc[jj][kk] = 0.f;

#pragma unroll 2
        for (int h = 0; h < HDIM; h += 4) {
            float4 a[8], bb[4];
#pragma unroll
            for (int jj = 0; jj < 8; jj++)
                a[jj] = *(const float4*)&As[(ty * 8 + jj) * A_STRIDE + h];
#pragma unroll
            for (int hh = 0; hh < 4; hh++)
                bb[hh] = *(const float4*)&Bs[(h + hh) * B_STRIDE + tx * 4];
#pragma unroll
            for (int jj = 0; jj < 8; jj++) {
                float av0 = a[jj].x, av1 = a[jj].y, av2 = a[jj].z, av3 = a[jj].w;
                acc[jj][0] = fmaf(av0, bb[0].x, acc[jj][0]);
                acc[jj][1] = fmaf(av0, bb[0].y, acc[jj][1]);
                acc[jj][2] = fmaf(av0, bb[0].z, acc[jj][2]);
                acc[jj][3] = fmaf(av0, bb[0].w, acc[jj][3]);
                acc[jj][0] = fmaf(av1, bb[1].x, acc[jj][0]);
                acc[jj][1] = fmaf(av1, bb[1].y, acc[jj][1]);
                acc[jj][2] = fmaf(av1, bb[1].z, acc[jj][2]);
                acc[jj][3] = fmaf(av1, bb[1].w, acc[jj][3]);
                acc[jj][0] = fmaf(av2, bb[2].x, acc[jj][0]);
                acc[jj][1] = fmaf(av2, bb[2].y, acc[jj][1]);
                acc[jj][2] = fmaf(av2, bb[2].z, acc[jj][2]);
                acc[jj][3] = fmaf(av2, bb[2].w, acc[jj][3]);
                acc[jj][0] = fmaf(av3, bb[3].x, acc[jj][0]);
                acc[jj][1] = fmaf(av3, bb[3].y, acc[jj][1]);
                acc[jj][2] = fmaf(av3, bb[3].z, acc[jj][2]);
                acc[jj][3] = fmaf(av3, bb[3].w, acc[jj][3]);
            }
        }

        // fused epilogue: relu + dot(w_score) partial, reduce over tx
        const int k0 = kc + tx * 4;
        float base4[4] = {base_s[k0], base_s[k0 + 1], base_s[k0 + 2], base_s[k0 + 3]};
        float w4[4]    = {wsc_s[k0],  wsc_s[k0 + 1],  wsc_s[k0 + 2],  wsc_s[k0 + 3]};
#pragma unroll
        for (int jj = 0; jj < 8; jj++) {
            int j = ty * 8 + jj;
            float4 xwv = *(const float4*)&xwb[j * HDIM + k0];
            float xa[4] = {xwv.x, xwv.y, xwv.z, xwv.w};
            float p = 0.f;
#pragma unroll
            for (int kk = 0; kk < 4; kk++) {
                float u = acc[jj][kk] + base4[kk] + xa[kk];
                p = fmaf(fmaxf(u, 0.f), w4[kk], p);
            }
            // reduce across the 16 tx lanes (xor within 16-lane half-warp)
            p += __shfl_xor_sync(0xffffffffu, p, 8);
            p += __shfl_xor_sync(0xffffffffu, p, 4);
            p += __shfl_xor_sync(0xffffffffu, p, 2);
            p += __shfl_xor_sync(0xffffffffu, p, 1);
            if (tx == 0) score_s[j] += p;
        }
    }

    __syncthreads();
    // S = sum_j score[j] + N * b_score
    if (t < NDIM) {
        float S = score_s[t];
        S += __shfl_xor_sync(0xffffffffu, S, 16);
        S += __shfl_xor_sync(0xffffffffu, S, 8);
        S += __shfl_xor_sync(0xffffffffu, S, 4);
        S += __shfl_xor_sync(0xffffffffu, S, 2);
        S += __shfl_xor_sync(0xffffffffu, S, 1);
        if ((t & 31) == 0) red_s[t >> 5] = S;
    }
    __syncthreads();
    if (t == 0)
        red_s[4] = red_s[0] + red_s[1] + red_s[2] + red_s[3] + (float)NDIM * b_score[0];
    __syncthreads();

    out_ctx[bi * HDIM + t] = ini_s[t] * red_s[4];
}

// ---------------------------------------------------------------------------
extern "C" void kernel_launch(void* const* d_in, const int* in_sizes, int n_in,
                              void* d_out, int out_size)
{
    const float* inputs       = (const float*)d_in[0];
    const float* bin_features = (const float*)d_in[1];
    const float* W_atom       = (const float*)d_in[2];
    const float* W_bin        = (const float*)d_in[3];
    const float* b_bin        = (const float*)d_in[4];
    const float* w_score      = (const float*)d_in[5];
    const float* b_score      = (const float*)d_in[6];

    float* out_ctx  = (float*)d_out;                       // [B,N,H]
    float* out_pair = out_ctx + BDIM * NDIM * HDIM;        // [B,N,N,H]

    const int smem_floats = NDIM * A_STRIDE + HDIM * B_STRIDE + 3 * HDIM + NDIM + 8;
    const int smem_bytes  = smem_floats * (int)sizeof(float);

    static bool attr_set = false;
    if (!attr_set) {
        cudaFuncSetAttribute(main_kernel, cudaFuncAttributeMaxDynamicSharedMemorySize,
                             smem_bytes);
        attr_set = true;
    }

    xw_kernel<<<(BDIM * NDIM) / 4, 256>>>(inputs, W_atom);
    main_kernel<<<BDIM * NDIM, 256, smem_bytes>>>(
        inputs, bin_features, W_bin, b_bin, w_score, b_score, out_ctx, out_pair);
}

// round 3
// speedup vs baseline: 1.5417x; 1.5417x over previous
#include <cuda_runtime.h>
#include <cuda_bf16.h>
#include <cstdint>

#define BDIM 16
#define NDIM 128
#define HDIM 256

#define ASTR 264     // A smem row stride (bf16 elems), padded: conflict-free ldmatrix
#define BSTR 72      // B smem row stride (bf16 elems), padded

#define A_BYTES (128 * ASTR * 2)          // 67584 per split
#define B_BYTES (256 * BSTR * 2)          // 36864 per split
#define MISC_OFF (2 * A_BYTES + 2 * B_BYTES)   // 208896
#define SMEM_REQ (MISC_OFF + 4096)

// scratch: xw = inputs @ W_atom (2MB, L2-resident)
__device__ float g_xw[BDIM * NDIM * HDIM];
// bf16 hi/lo images of W_bin column-chunks: [chunk][h=256][n=64]
__device__ __align__(16) unsigned short g_Wh[4][HDIM * 64];
__device__ __align__(16) unsigned short g_Wl[4][HDIM * 64];

// ---------------------------------------------------------------------------
__device__ __forceinline__ uint32_t smem_u32(const void* p) {
    uint32_t a;
    asm("{ .reg .u64 t; cvta.to.shared.u64 t, %1; cvt.u32.u64 %0, t; }" : "=r"(a) : "l"(p));
    return a;
}
__device__ __forceinline__ void ldsm_x4(uint32_t* r, uint32_t addr) {
    asm volatile("ldmatrix.sync.aligned.m8n8.x4.shared.b16 {%0,%1,%2,%3}, [%4];"
        : "=r"(r[0]), "=r"(r[1]), "=r"(r[2]), "=r"(r[3]) : "r"(addr));
}
__device__ __forceinline__ void ldsm_x4_t(uint32_t* r, uint32_t addr) {
    asm volatile("ldmatrix.sync.aligned.m8n8.x4.trans.shared.b16 {%0,%1,%2,%3}, [%4];"
        : "=r"(r[0]), "=r"(r[1]), "=r"(r[2]), "=r"(r[3]) : "r"(addr));
}
__device__ __forceinline__ void mma16816(float* d, const uint32_t* a, const uint32_t* b) {
    asm volatile("mma.sync.aligned.m16n8k16.row.col.f32.bf16.bf16.f32 "
        "{%0,%1,%2,%3}, {%4,%5,%6,%7}, {%8,%9}, {%0,%1,%2,%3};"
        : "+f"(d[0]), "+f"(d[1]), "+f"(d[2]), "+f"(d[3])
        : "r"(a[0]), "r"(a[1]), "r"(a[2]), "r"(a[3]), "r"(b[0]), "r"(b[1]));
}
__device__ __forceinline__ void bf16_split(float v, uint16_t& hi, uint16_t& lo) {
    __nv_bfloat16 h = __float2bfloat16(v);
    __nv_bfloat16 l = __float2bfloat16(v - __bfloat162float(h));
    hi = __bfloat16_as_ushort(h);
    lo = __bfloat16_as_ushort(l);
}

// ---------------------------------------------------------------------------
// Kernel 1: xw[b,n,k] = sum_h inputs[b,n,h] * W_atom[h,k]
// ---------------------------------------------------------------------------
__global__ void __launch_bounds__(256, 4) xw_kernel(
    const float* __restrict__ inputs, const float* __restrict__ W_atom)
{
    __shared__ float s_in[4][HDIM];
    int row0 = blockIdx.x * 4;
    int t = threadIdx.x;
#pragma unroll
    for (int r = 0; r < 4; r++) s_in[r][t] = inputs[(row0 + r) * HDIM + t];
    __syncthreads();

    float a0 = 0.f, a1 = 0.f, a2 = 0.f, a3 = 0.f;
#pragma unroll 8
    for (int h = 0; h < HDIM; h++) {
        float w = W_atom[h * HDIM + t];
        a0 = fmaf(s_in[0][h], w, a0);
        a1 = fmaf(s_in[1][h], w, a1);
        a2 = fmaf(s_in[2][h], w, a2);
        a3 = fmaf(s_in[3][h], w, a3);
    }
    g_xw[(row0 + 0) * HDIM + t] = a0;
    g_xw[(row0 + 1) * HDIM + t] = a1;
    g_xw[(row0 + 2) * HDIM + t] = a2;
    g_xw[(row0 + 3) * HDIM + t] = a3;
}

// ---------------------------------------------------------------------------
// Kernel 2: split W_bin into bf16 hi/lo column-chunk images [c][h][64]
// ---------------------------------------------------------------------------
__global__ void __launch_bounds__(256) prep_w(const float* __restrict__ W_bin)
{
    int idx = blockIdx.x * 256 + threadIdx.x;   // 0..65535
    int c  = idx >> 14;
    int r  = idx & 16383;
    int h  = r >> 6;
    int nc = r & 63;
    float v = W_bin[h * HDIM + c * 64 + nc];
    uint16_t hi, lo;
    bf16_split(v, hi, lo);
    g_Wh[c][h * 64 + nc] = hi;
    g_Wl[c][h * 64 + nc] = lo;
}

// ---------------------------------------------------------------------------
// Kernel 3: one CTA per (b,i). HMMA bf16-split GEMM, fully fused epilogue.
//   D[j,n] = bin[b,i] @ W_bin ; score[j] = sum_n relu(D + xw_i + b_bin + xw_j)*w_score
//   out_ctx[b,i,:] = inputs[b,i,:] * (sum_j score[j] + N*b_score)
//   out_pair[b,i,j,:] = inputs[b,i,:] + inputs[b,j,:]
// ---------------------------------------------------------------------------
extern __shared__ unsigned char smraw[];

__global__ void __launch_bounds__(256, 1) main_kernel(
    const float* __restrict__ inputs,
    const float* __restrict__ bin_features,
    const float* __restrict__ b_bin,
    const float* __restrict__ w_score,
    const float* __restrict__ b_score,
    float* __restrict__ out_ctx,
    float* __restrict__ out_pair)
{
    const int bi   = blockIdx.x;         // b*128 + i
    const int b    = bi >> 7;
    const int t    = threadIdx.x;
    const int warp = t >> 5;
    const int lane = t & 31;
    const int w_m  = warp >> 1;          // 0..3  (32 rows each)
    const int w_n  = warp & 1;           // 0..1  (32 cols each)

    __nv_bfloat16* A_hi = (__nv_bfloat16*)smraw;            // [128][ASTR]
    __nv_bfloat16* A_lo = A_hi + 128 * ASTR;
    __nv_bfloat16* B_hi = A_lo + 128 * ASTR;                 // [256][BSTR]
    __nv_bfloat16* B_lo = B_hi + 256 * BSTR;
    float* base_s  = (float*)(smraw + MISC_OFF);   // xw_i + b_bin  [256]
    float* wsc_s   = base_s + HDIM;                // w_score       [256]
    float* ini_s   = wsc_s + HDIM;                 // inputs[b,i,:] [256]
    float* score_s = ini_s + HDIM;                 // [128]
    float* red_s   = score_s + NDIM;               // [8]

    // small smem fills
    base_s[t] = g_xw[bi * HDIM + t] + b_bin[t];
    wsc_s[t]  = w_score[t];
    ini_s[t]  = inputs[bi * HDIM + t];
    if (t < NDIM) score_s[t] = 0.f;

    // A: bin[b,i] fp32 -> bf16 hi/lo into padded smem
    const float4* gA = (const float4*)(bin_features + (size_t)bi * NDIM * HDIM);
#pragma unroll
    for (int r = 0; r < 32; r++) {
        int f = t + r * 256;             // 0..8191 float4
        int j = f >> 6, q = f & 63;
        float4 v = gA[f];
        uint16_t h0, l0, h1, l1, h2, l2, h3, l3;
        bf16_split(v.x, h0, l0); bf16_split(v.y, h1, l1);
        bf16_split(v.z, h2, l2); bf16_split(v.w, h3, l3);
        uint2 hv = { (uint32_t)h0 | ((uint32_t)h1 << 16),
                     (uint32_t)h2 | ((uint32_t)h3 << 16) };
        uint2 lv = { (uint32_t)l0 | ((uint32_t)l1 << 16),
                     (uint32_t)l2 | ((uint32_t)l3 << 16) };
        *(uint2*)&A_hi[j * ASTR + q * 4] = hv;
        *(uint2*)&A_lo[j * ASTR + q * 4] = lv;
    }

    const float4* gin  = (const float4*)(inputs + (size_t)b * NDIM * HDIM);
    float4*       gpr  = (float4*)(out_pair + (size_t)bi * NDIM * HDIM);
    const float4* ini4 = (const float4*)ini_s;
    const float*  xwb  = g_xw + (size_t)(b * NDIM) * HDIM;

    // per-lane ldmatrix offsets (bytes)
    const uint32_t sa_hi = smem_u32(A_hi), sa_lo = smem_u32(A_lo);
    const uint32_t sb_hi = smem_u32(B_hi), sb_lo = smem_u32(B_lo);
    const uint32_t a_lane = (uint32_t)(((w_m * 32 + (lane & 15)) * ASTR + ((lane >> 4) << 3)) * 2);
    const uint32_t b_lane = (uint32_t)(((lane & 15) * BSTR + (w_n * 32 + ((lane >> 4) << 3))) * 2);
    const int g4 = lane >> 2, t4 = lane & 3;

    for (int c = 0; c < 4; c++) {
        __syncthreads();   // prior chunk's MMAs done reading B (and A/misc ready on c=0)

        // B chunk hi/lo -> padded smem rows (thread t copies row h=t: 8 uint4 each)
        {
            const uint4* sh = (const uint4*)&g_Wh[c][0];
            const uint4* sl = (const uint4*)&g_Wl[c][0];
            uint4* dh = (uint4*)&B_hi[t * BSTR];
            uint4* dl = (uint4*)&B_lo[t * BSTR];
#pragma unroll
            for (int q = 0; q < 8; q++) { dh[q] = sh[t * 8 + q]; dl[q] = sl[t * 8 + q]; }
        }

        // atom_pair: this chunk's quarter of the 128KB write (overlaps with MMA)
#pragma unroll
        for (int r = 0; r < 8; r++) {
            int g = (c << 11) + t + r * 256;
            int j = g >> 6, q = g & 63;
            float4 a = ini4[q];
            float4 x = gin[(j << 6) + q];
            a.x += x.x; a.y += x.y; a.z += x.z; a.w += x.w;
            gpr[g] = a;
        }

        __syncthreads();

        float acc[2][4][4];
#pragma unroll
        for (int tm = 0; tm < 2; tm++)
#pragma unroll
            for (int tn = 0; tn < 4; tn++)
#pragma unroll
                for (int e = 0; e < 4; e++) acc[tm][tn][e] = 0.f;

#pragma unroll 4
        for (int ks = 0; ks < 16; ks++) {
            const int k0 = ks * 16;
            uint32_t ahi[2][4], alo[2][4], bhi[2][4], blo[2][4];
#pragma unroll
            for (int tm = 0; tm < 2; tm++) {
                uint32_t off = a_lane + (uint32_t)((tm * 16 * ASTR + k0) * 2);
                ldsm_x4(ahi[tm], sa_hi + off);
                ldsm_x4(alo[tm], sa_lo + off);
            }
#pragma unroll
            for (int nt = 0; nt < 2; nt++) {
                uint32_t off = b_lane + (uint32_t)((k0 * BSTR + nt * 16) * 2);
                ldsm_x4_t(bhi[nt], sb_hi + off);
                ldsm_x4_t(blo[nt], sb_lo + off);
            }
#pragma unroll
            for (int tm = 0; tm < 2; tm++)
#pragma unroll
                for (int tn = 0; tn < 4; tn++) {
                    const int nt = tn >> 1, hf = (tn & 1) * 2;
                    mma16816(acc[tm][tn], ahi[tm], &bhi[nt][hf]);
                    mma16816(acc[tm][tn], ahi[tm], &blo[nt][hf]);
                    mma16816(acc[tm][tn], alo[tm], &bhi[nt][hf]);
                }
        }

        // fused epilogue on register fragments:
        // score[j] += sum_n relu(acc + base[n] + xw[j,n]) * w_score[n]
        const int Cb = c * 64 + w_n * 32;
#pragma unroll
        for (int tm = 0; tm < 2; tm++) {
            const int j0 = w_m * 32 + tm * 16 + g4;
            const int j1 = j0 + 8;
            float p0 = 0.f, p1 = 0.f;
#pragma unroll
            for (int tn = 0; tn < 4; tn++) {
                const int n0 = Cb + tn * 8 + t4 * 2;
                float2 bw = *(const float2*)&base_s[n0];
                float2 wv = *(const float2*)&wsc_s[n0];
                float2 x0 = *(const float2*)&xwb[(size_t)j0 * HDIM + n0];
                float2 x1 = *(const float2*)&xwb[(size_t)j1 * HDIM + n0];
                const float* a = acc[tm][tn];
                p0 = fmaf(fmaxf(a[0] + bw.x + x0.x, 0.f), wv.x, p0);
                p0 = fmaf(fmaxf(a[1] + bw.y + x0.y, 0.f), wv.y, p0);
                p1 = fmaf(fmaxf(a[2] + bw.x + x1.x, 0.f), wv.x, p1);
                p1 = fmaf(fmaxf(a[3] + bw.y + x1.y, 0.f), wv.y, p1);
            }
            p0 += __shfl_xor_sync(0xffffffffu, p0, 1);
            p0 += __shfl_xor_sync(0xffffffffu, p0, 2);
            p1 += __shfl_xor_sync(0xffffffffu, p1, 1);
            p1 += __shfl_xor_sync(0xffffffffu, p1, 2);
            if (t4 == 0) {
                atomicAdd(&score_s[j0], p0);
                atomicAdd(&score_s[j1], p1);
            }
        }
    }

    __syncthreads();
    if (t < NDIM) {
        float S = score_s[t];
        S += __shfl_xor_sync(0xffffffffu, S, 16);
        S += __shfl_xor_sync(0xffffffffu, S, 8);
        S += __shfl_xor_sync(0xffffffffu, S, 4);
        S += __shfl_xor_sync(0xffffffffu, S, 2);
        S += __shfl_xor_sync(0xffffffffu, S, 1);
        if ((t & 31) == 0) red_s[t >> 5] = S;
    }
    __syncthreads();
    if (t == 0)
        red_s[4] = red_s[0] + red_s[1] + red_s[2] + red_s[3]
                 + (float)NDIM * b_score[0];
    __syncthreads();

    out_ctx[bi * HDIM + t] = ini_s[t] * red_s[4];
}

// ---------------------------------------------------------------------------
extern "C" void kernel_launch(void* const* d_in, const int* in_sizes, int n_in,
                              void* d_out, int out_size)
{
    const float* inputs       = (const float*)d_in[0];
    const float* bin_features = (const float*)d_in[1];
    const float* W_atom       = (const float*)d_in[2];
    const float* W_bin        = (const float*)d_in[3];
    const float* b_bin        = (const float*)d_in[4];
    const float* w_score      = (const float*)d_in[5];
    const float* b_score      = (const float*)d_in[6];

    float* out_ctx  = (float*)d_out;                   // [B,N,H]
    float* out_pair = out_ctx + BDIM * NDIM * HDIM;    // [B,N,N,H]

    static bool attr_set = false;
    if (!attr_set) {
        cudaFuncSetAttribute(main_kernel, cudaFuncAttributeMaxDynamicSharedMemorySize,
                             SMEM_REQ);
        attr_set = true;
    }

    xw_kernel<<<(BDIM * NDIM) / 4, 256>>>(inputs, W_atom);
    prep_w<<<256, 256>>>(W_bin);
    main_kernel<<<BDIM * NDIM, 256, SMEM_REQ>>>(
        inputs, bin_features, b_bin, w_score, b_score, out_ctx, out_pair);
}

// round 5
// speedup vs baseline: 1.9019x; 1.2337x over previous
#include <cuda_runtime.h>
#include <cuda_bf16.h>
#include <cstdint>

#define BDIM 16
#define NDIM 128
#define HDIM 256

#define ASTR 264     // A smem row stride (bf16 elems), padded: conflict-free ldmatrix
#define BSTR 72      // B smem row stride (bf16 elems), padded

#define A_BYTES (128 * ASTR * 2)               // 67584 per split
#define B_BYTES (256 * BSTR * 2)               // 36864 per split
#define MISC_OFF (2 * A_BYTES + 2 * B_BYTES)   // 208896
#define SMEM_REQ (MISC_OFF + 8192)             // misc region needs 4128B; pad to 8K

#define NTHR 512

// scratch: xw = inputs @ W_atom (2MB, L2-resident)
__device__ float g_xw[BDIM * NDIM * HDIM];
// bf16 hi/lo images of W_bin column-chunks: [chunk][h=256][n=64]
__device__ __align__(16) unsigned short g_Wh[4][HDIM * 64];
__device__ __align__(16) unsigned short g_Wl[4][HDIM * 64];

// ---------------------------------------------------------------------------
__device__ __forceinline__ uint32_t smem_u32(const void* p) {
    uint32_t a;
    asm("{ .reg .u64 t; cvta.to.shared.u64 t, %1; cvt.u32.u64 %0, t; }" : "=r"(a) : "l"(p));
    return a;
}
__device__ __forceinline__ void ldsm_x4(uint32_t* r, uint32_t addr) {
    asm volatile("ldmatrix.sync.aligned.m8n8.x4.shared.b16 {%0,%1,%2,%3}, [%4];"
        : "=r"(r[0]), "=r"(r[1]), "=r"(r[2]), "=r"(r[3]) : "r"(addr));
}
__device__ __forceinline__ void ldsm_x4_t(uint32_t* r, uint32_t addr) {
    asm volatile("ldmatrix.sync.aligned.m8n8.x4.trans.shared.b16 {%0,%1,%2,%3}, [%4];"
        : "=r"(r[0]), "=r"(r[1]), "=r"(r[2]), "=r"(r[3]) : "r"(addr));
}
__device__ __forceinline__ void mma16816(float* d, const uint32_t* a, const uint32_t* b) {
    asm volatile("mma.sync.aligned.m16n8k16.row.col.f32.bf16.bf16.f32 "
        "{%0,%1,%2,%3}, {%4,%5,%6,%7}, {%8,%9}, {%0,%1,%2,%3};"
        : "+f"(d[0]), "+f"(d[1]), "+f"(d[2]), "+f"(d[3])
        : "r"(a[0]), "r"(a[1]), "r"(a[2]), "r"(a[3]), "r"(b[0]), "r"(b[1]));
}
__device__ __forceinline__ void bf16_split(float v, uint16_t& hi, uint16_t& lo) {
    __nv_bfloat16 h = __float2bfloat16(v);
    __nv_bfloat16 l = __float2bfloat16(v - __bfloat162float(h));
    hi = __bfloat16_as_ushort(h);
    lo = __bfloat16_as_ushort(l);
}

// ---------------------------------------------------------------------------
// Kernel 1: xw[b,n,k] = sum_h inputs[b,n,h] * W_atom[h,k]
// ---------------------------------------------------------------------------
__global__ void __launch_bounds__(256, 4) xw_kernel(
    const float* __restrict__ inputs, const float* __restrict__ W_atom)
{
    __shared__ float s_in[4][HDIM];
    int row0 = blockIdx.x * 4;
    int t = threadIdx.x;
#pragma unroll
    for (int r = 0; r < 4; r++) s_in[r][t] = inputs[(row0 + r) * HDIM + t];
    __syncthreads();

    float a0 = 0.f, a1 = 0.f, a2 = 0.f, a3 = 0.f;
#pragma unroll 8
    for (int h = 0; h < HDIM; h++) {
        float w = W_atom[h * HDIM + t];
        a0 = fmaf(s_in[0][h], w, a0);
        a1 = fmaf(s_in[1][h], w, a1);
        a2 = fmaf(s_in[2][h], w, a2);
        a3 = fmaf(s_in[3][h], w, a3);
    }
    g_xw[(row0 + 0) * HDIM + t] = a0;
    g_xw[(row0 + 1) * HDIM + t] = a1;
    g_xw[(row0 + 2) * HDIM + t] = a2;
    g_xw[(row0 + 3) * HDIM + t] = a3;
}

// ---------------------------------------------------------------------------
// Kernel 2: split W_bin into bf16 hi/lo column-chunk images [c][h][64]
// ---------------------------------------------------------------------------
__global__ void __launch_bounds__(256) prep_w(const float* __restrict__ W_bin)
{
    int idx = blockIdx.x * 256 + threadIdx.x;   // 0..65535
    int c  = idx >> 14;
    int r  = idx & 16383;
    int h  = r >> 6;
    int nc = r & 63;
    float v = W_bin[h * HDIM + c * 64 + nc];
    uint16_t hi, lo;
    bf16_split(v, hi, lo);
    g_Wh[c][h * 64 + nc] = hi;
    g_Wl[c][h * 64 + nc] = lo;
}

// ---------------------------------------------------------------------------
// Kernel 3: one CTA per (b,i). 16 warps, warp tile m16 x n32, bf16-split HMMA.
// ---------------------------------------------------------------------------
extern __shared__ unsigned char smraw[];

__global__ void __launch_bounds__(NTHR, 1) main_kernel(
    const float* __restrict__ inputs,
    const float* __restrict__ bin_features,
    const float* __restrict__ b_bin,
    const float* __restrict__ w_score,
    const float* __restrict__ b_score,
    float* __restrict__ out_ctx,
    float* __restrict__ out_pair)
{
    const int bi   = blockIdx.x;         // b*128 + i
    const int b    = bi >> 7;
    const int t    = threadIdx.x;
    const int warp = t >> 5;             // 0..15
    const int lane = t & 31;
    const int w_m  = warp >> 1;          // 0..7  (16 rows each)
    const int w_n  = warp & 1;           // 0..1  (32 cols each)
    const int g4   = lane >> 2, t4 = lane & 3;

    __nv_bfloat16* A_hi = (__nv_bfloat16*)smraw;            // [128][ASTR]
    __nv_bfloat16* A_lo = A_hi + 128 * ASTR;
    __nv_bfloat16* B_hi = A_lo + 128 * ASTR;                 // [256][BSTR]
    __nv_bfloat16* B_lo = B_hi + 256 * BSTR;
    float* base_s  = (float*)(smraw + MISC_OFF);   // xw_i + b_bin  [256]
    float* wsc_s   = base_s + HDIM;                // w_score       [256]
    float* ini_s   = wsc_s + HDIM;                 // inputs[b,i,:] [256]
    float* score_s = ini_s + HDIM;                 // [2][128]
    float* red_s   = score_s + 2 * NDIM;           // [8]

    // small smem fills
    if (t < HDIM) {
        base_s[t] = g_xw[bi * HDIM + t] + b_bin[t];
        wsc_s[t]  = w_score[t];
        ini_s[t]  = inputs[bi * HDIM + t];
    }

    // A: bin[b,i] fp32 -> bf16 hi/lo into padded smem
    const float4* gA = (const float4*)(bin_features + (size_t)bi * NDIM * HDIM);
#pragma unroll
    for (int r = 0; r < 16; r++) {
        int f = t + r * NTHR;            // 0..8191 float4
        int j = f >> 6, q = f & 63;
        float4 v = gA[f];
        uint16_t h0, l0, h1, l1, h2, l2, h3, l3;
        bf16_split(v.x, h0, l0); bf16_split(v.y, h1, l1);
        bf16_split(v.z, h2, l2); bf16_split(v.w, h3, l3);
        uint2 hv = { (uint32_t)h0 | ((uint32_t)h1 << 16),
                     (uint32_t)h2 | ((uint32_t)h3 << 16) };
        uint2 lv = { (uint32_t)l0 | ((uint32_t)l1 << 16),
                     (uint32_t)l2 | ((uint32_t)l3 << 16) };
        *(uint2*)&A_hi[j * ASTR + q * 4] = hv;
        *(uint2*)&A_lo[j * ASTR + q * 4] = lv;
    }

    const float4* gin  = (const float4*)(inputs + (size_t)b * NDIM * HDIM);
    float4*       gpr  = (float4*)(out_pair + (size_t)bi * NDIM * HDIM);
    const float4* ini4 = (const float4*)ini_s;
    const float*  xwb  = g_xw + (size_t)(b * NDIM) * HDIM;

    // per-lane ldmatrix byte offsets
    const uint32_t sa_hi = smem_u32(A_hi), sa_lo = smem_u32(A_lo);
    const uint32_t sb_hi = smem_u32(B_hi), sb_lo = smem_u32(B_lo);
    const uint32_t a_lane = (uint32_t)(((w_m * 16 + (lane & 15)) * ASTR + ((lane >> 4) << 3)) * 2);
    const uint32_t b_lane = (uint32_t)(((lane & 15) * BSTR + w_n * 32 + ((lane >> 4) << 3)) * 2);

    // per-warp running scores for its two j rows (j0 = w_m*16+g4, j1 = j0+8)
    float sc0 = 0.f, sc1 = 0.f;
    const int j0 = w_m * 16 + g4;
    const int j1 = j0 + 8;

    for (int c = 0; c < 4; c++) {
        __syncthreads();   // prior chunk's MMAs done reading B

        // B chunk hi/lo -> padded smem rows (2 threads per row h)
        {
            const uint4* sh = (const uint4*)&g_Wh[c][0];
            const uint4* sl = (const uint4*)&g_Wl[c][0];
            int h = t >> 1, half = t & 1;
            uint4* dh = (uint4*)&B_hi[h * BSTR] + half * 4;
            uint4* dl = (uint4*)&B_lo[h * BSTR] + half * 4;
            const uint4* shh = sh + h * 8 + half * 4;
            const uint4* sll = sl + h * 8 + half * 4;
#pragma unroll
            for (int q = 0; q < 4; q++) { dh[q] = shh[q]; dl[q] = sll[q]; }
        }

        // atom_pair: this chunk's quarter of the 128KB write (overlaps with MMA)
#pragma unroll
        for (int r = 0; r < 4; r++) {
            int g = (c << 11) + t + r * NTHR;
            int j = g >> 6, q = g & 63;
            float4 a = ini4[q];
            float4 x = gin[(j << 6) + q];
            a.x += x.x; a.y += x.y; a.z += x.z; a.w += x.w;
            gpr[g] = a;
        }

        __syncthreads();

        float acc[4][4];
#pragma unroll
        for (int tn = 0; tn < 4; tn++)
#pragma unroll
            for (int e = 0; e < 4; e++) acc[tn][e] = 0.f;

#pragma unroll 4
        for (int ks = 0; ks < 16; ks++) {
            const int k0 = ks * 16;
            uint32_t ahi[4], alo[4], bhi[2][4], blo[2][4];
            {
                uint32_t off = a_lane + (uint32_t)(k0 * 2);
                ldsm_x4(ahi, sa_hi + off);
                ldsm_x4(alo, sa_lo + off);
            }
#pragma unroll
            for (int nt = 0; nt < 2; nt++) {
                uint32_t off = b_lane + (uint32_t)((k0 * BSTR + nt * 16) * 2);
                ldsm_x4_t(bhi[nt], sb_hi + off);
                ldsm_x4_t(blo[nt], sb_lo + off);
            }
#pragma unroll
            for (int tn = 0; tn < 4; tn++) {
                const int nt = tn >> 1, hf = (tn & 1) * 2;
                mma16816(acc[tn], ahi, &bhi[nt][hf]);
                mma16816(acc[tn], ahi, &blo[nt][hf]);
                mma16816(acc[tn], alo, &bhi[nt][hf]);
            }
        }

        // fused epilogue on fragments: running score in registers
        const int Cb = c * 64 + w_n * 32;
        float p0 = 0.f, p1 = 0.f;
#pragma unroll
        for (int tn = 0; tn < 4; tn++) {
            const int n0 = Cb + tn * 8 + t4 * 2;
            float2 bw = *(const float2*)&base_s[n0];
            float2 wv = *(const float2*)&wsc_s[n0];
            float2 x0 = *(const float2*)&xwb[(size_t)j0 * HDIM + n0];
            float2 x1 = *(const float2*)&xwb[(size_t)j1 * HDIM + n0];
            const float* a = acc[tn];
            p0 = fmaf(fmaxf(a[0] + bw.x + x0.x, 0.f), wv.x, p0);
            p0 = fmaf(fmaxf(a[1] + bw.y + x0.y, 0.f), wv.y, p0);
            p1 = fmaf(fmaxf(a[2] + bw.x + x1.x, 0.f), wv.x, p1);
            p1 = fmaf(fmaxf(a[3] + bw.y + x1.y, 0.f), wv.y, p1);
        }
        p0 += __shfl_xor_sync(0xffffffffu, p0, 1);
        p0 += __shfl_xor_sync(0xffffffffu, p0, 2);
        p1 += __shfl_xor_sync(0xffffffffu, p1, 1);
        p1 += __shfl_xor_sync(0xffffffffu, p1, 2);
        sc0 += p0;
        sc1 += p1;
    }

    // one plain store per (warp-half, j row) — no atomics
    if (t4 == 0) {
        score_s[w_n * NDIM + j0] = sc0;
        score_s[w_n * NDIM + j1] = sc1;
    }

    __syncthreads();
    if (t < NDIM) {
        float S = score_s[t] + score_s[NDIM + t];
        S += __shfl_xor_sync(0xffffffffu, S, 16);
        S += __shfl_xor_sync(0xffffffffu, S, 8);
        S += __shfl_xor_sync(0xffffffffu, S, 4);
        S += __shfl_xor_sync(0xffffffffu, S, 2);
        S += __shfl_xor_sync(0xffffffffu, S, 1);
        if ((t & 31) == 0) red_s[t >> 5] = S;
    }
    __syncthreads();
    if (t == 0)
        red_s[4] = red_s[0] + red_s[1] + red_s[2] + red_s[3]
                 + (float)NDIM * b_score[0];
    __syncthreads();

    if (t < HDIM)
        out_ctx[bi * HDIM + t] = ini_s[t] * red_s[4];
}

// ---------------------------------------------------------------------------
extern "C" void kernel_launch(void* const* d_in, const int* in_sizes, int n_in,
                              void* d_out, int out_size)
{
    const float* inputs       = (const float*)d_in[0];
    const float* bin_features = (const float*)d_in[1];
    const float* W_atom       = (const float*)d_in[2];
    const float* W_bin        = (const float*)d_in[3];
    const float* b_bin        = (const float*)d_in[4];
    const float* w_score      = (const float*)d_in[5];
    const float* b_score      = (const float*)d_in[6];

    float* out_ctx  = (float*)d_out;                   // [B,N,H]
    float* out_pair = out_ctx + BDIM * NDIM * HDIM;    // [B,N,N,H]

    static bool attr_set = false;
    if (!attr_set) {
        cudaFuncSetAttribute(main_kernel, cudaFuncAttributeMaxDynamicSharedMemorySize,
                             SMEM_REQ);
        attr_set = true;
    }

    xw_kernel<<<(BDIM * NDIM) / 4, 256>>>(inputs, W_atom);
    prep_w<<<256, 256>>>(W_bin);
    main_kernel<<<BDIM * NDIM, NTHR, SMEM_REQ>>>(
        inputs, bin_features, b_bin, w_score, b_score, out_ctx, out_pair);
}